// round 9
// baseline (speedup 1.0000x reference)
#include <cuda_runtime.h>
#include <cuda_fp16.h>
#include <cstdint>

#define SPARSITY 0.01f
#define BATCH 8
#define NN    2048
#define DIN   256
#define DOUT  256

__device__ __half g_ST[BATCH * DOUT * NN];   // support^T fp16: [b][col][node]
__device__ __half g_WT[DOUT * DIN];          // sign(quant(W))^T fp16
__device__ __half g_X16[BATCH * NN * DIN];   // x fp16

__device__ __forceinline__ uint32_t smem_u32(const void* p) {
    uint32_t a;
    asm("{ .reg .u64 t; cvta.to.shared.u64 t, %1; cvt.u32.u64 %0, t; }"
        : "=r"(a) : "l"(p));
    return a;
}

// ---------------- fused prep: quantW transpose (blocks 0-63) + x->fp16 ------
__global__ void __launch_bounds__(256) prep_kernel(
    const float* __restrict__ W, __half* __restrict__ WT,
    const float* __restrict__ x, __half* __restrict__ x16)
{
    const int bid = blockIdx.x;
    const int t = threadIdx.x;
    if (bid < 64) {
        __shared__ float tile[32][33];
        const int tx = t & 31, ty = t >> 5;
        const int o0 = (bid & 7) * 32;
        const int i0 = (bid >> 3) * 32;
        #pragma unroll
        for (int j = ty; j < 32; j += 8) {
            float w = W[(size_t)(i0 + j) * DOUT + o0 + tx];
            tile[j][tx] = (w > SPARSITY ? 1.0f : 0.0f) + (w < -SPARSITY ? -1.0f : 0.0f);
        }
        __syncthreads();
        #pragma unroll
        for (int j = ty; j < 32; j += 8)
            WT[(size_t)(o0 + j) * DIN + i0 + tx] = __float2half_rn(tile[tx][j]);
    } else {
        const size_t i = ((size_t)(bid - 64) * 256 + t) * 8;
        float4 a = *(const float4*)(x + i);
        float4 b = *(const float4*)(x + i + 4);
        __half2 h[4];
        h[0] = __floats2half2_rn(a.x, a.y);
        h[1] = __floats2half2_rn(a.z, a.w);
        h[2] = __floats2half2_rn(b.x, b.y);
        h[3] = __floats2half2_rn(b.z, b.w);
        *(uint4*)(x16 + i) = *(const uint4*)h;
    }
}

// ---------------- common mma helpers ----------------------------------------
#define TK 32
__device__ __forceinline__ uint32_t swz16(int row, int c) {
    return (uint32_t)(row * 64 + ((c ^ ((row >> 1) & 3)) << 4));
}
__device__ __forceinline__ void ldsm4(uint32_t& r0, uint32_t& r1, uint32_t& r2,
                                      uint32_t& r3, uint32_t addr) {
    asm volatile("ldmatrix.sync.aligned.m8n8.x4.shared.b16 {%0,%1,%2,%3}, [%4];"
                 : "=r"(r0), "=r"(r1), "=r"(r2), "=r"(r3) : "r"(addr));
}
__device__ __forceinline__ void mma_f16(float* d, uint32_t a0, uint32_t a1,
                                        uint32_t a2, uint32_t a3,
                                        uint32_t b0, uint32_t b1) {
    asm volatile(
        "mma.sync.aligned.m16n8k16.row.col.f32.f16.f16.f32 "
        "{%0,%1,%2,%3}, {%4,%5,%6,%7}, {%8,%9}, {%0,%1,%2,%3};"
        : "+f"(d[0]), "+f"(d[1]), "+f"(d[2]), "+f"(d[3])
        : "r"(a0), "r"(a1), "r"(a2), "r"(a3), "r"(b0), "r"(b1));
}
__device__ __forceinline__ void cpasync16(uint32_t dst, const void* src) {
    asm volatile("cp.async.cg.shared.global [%0], [%1], 16;" :: "r"(dst), "l"(src));
}

// ============================================================================
// GEMM1: ST[b] = (signW @ x[b]^T) * s.  M=256, N=2048, K=256, all fp16 in.
// CTA 64x256x32, 8 warps 2Mx4N (warp 32x64), 3-stage pipeline.
// ============================================================================
#define B_STAGE 16384
#define A_TILE1 4096
#define G1_STG  (A_TILE1 + B_STAGE)
#define G1_SM   (3 * G1_STG)

__global__ void __launch_bounds__(256, 2) gemm1_kernel(
    const __half* __restrict__ WT,
    const __half* __restrict__ X16,
    __half* __restrict__ ST)
{
    extern __shared__ char smem[];
    const uint32_t sb = smem_u32(smem);
    const int t = threadIdx.x, wid = t >> 5, lane = t & 31;
    const int bm = blockIdx.x * 64;
    const int bn = blockIdx.y * 256;
    const int b  = blockIdx.z;

    const __half* Bg = X16 + (size_t)b * NN * DIN;
    const int M0 = (wid & 1) * 32;
    const int N0 = (wid >> 1) * 64;
    const int lrow = t >> 2, lc = t & 3;

    float acc[2][8][4] = {};

    auto load_stage = [&](int it, int slot) {
        const int k0 = it * TK;
        const uint32_t s0 = sb + slot * G1_STG;
        cpasync16(s0 + swz16(lrow, lc), WT + (size_t)(bm + lrow) * DIN + k0 + (lc << 3));
        #pragma unroll
        for (int i = 0; i < 4; i++) {
            int idx = t + 256 * i;
            int r = idx >> 2, c = idx & 3;
            cpasync16(s0 + A_TILE1 + swz16(r, c),
                      Bg + (size_t)(bn + r) * DIN + k0 + (c << 3));
        }
        asm volatile("cp.async.commit_group;");
    };

    load_stage(0, 0);
    load_stage(1, 1);
    asm volatile("cp.async.wait_group 1;");
    __syncthreads();

    const int g = lane >> 3, l7 = lane & 7;
    const int KITERS = DIN / TK;   // 8

    for (int it = 0; it < KITERS; it++) {
        if (it + 2 < KITERS) load_stage(it + 2, (it + 2) % 3);
        else asm volatile("cp.async.commit_group;");

        const uint32_t abase = sb + (it % 3) * G1_STG;
        const uint32_t bbase = abase + A_TILE1;

        #pragma unroll
        for (int ks = 0; ks < 2; ks++) {
            uint32_t a[2][4];
            #pragma unroll
            for (int mf = 0; mf < 2; mf++) {
                int row = M0 + mf * 16 + ((g & 1) << 3) + l7;
                int ch  = ks * 2 + (g >> 1);
                ldsm4(a[mf][0], a[mf][1], a[mf][2], a[mf][3], abase + swz16(row, ch));
            }
            uint32_t bf[8][2];
            #pragma unroll
            for (int j8 = 0; j8 < 4; j8++) {
                int row = N0 + j8 * 16 + ((g >> 1) << 3) + l7;
                int ch  = ks * 2 + (g & 1);
                uint32_t r0, r1, r2, r3;
                ldsm4(r0, r1, r2, r3, bbase + swz16(row, ch));
                bf[j8 * 2][0] = r0; bf[j8 * 2][1] = r1;
                bf[j8 * 2 + 1][0] = r2; bf[j8 * 2 + 1][1] = r3;
            }
            #pragma unroll
            for (int mf = 0; mf < 2; mf++)
                #pragma unroll
                for (int nf = 0; nf < 8; nf++)
                    mma_f16(acc[mf][nf], a[mf][0], a[mf][1], a[mf][2], a[mf][3],
                            bf[nf][0], bf[nf][1]);
        }
        asm volatile("cp.async.wait_group 1;");
        __syncthreads();
    }

    const int rq = lane >> 2, cq = lane & 3;
    __half* Cg = ST + (size_t)b * DOUT * NN;
    #pragma unroll
    for (int nf = 0; nf < 8; nf++) {
        const int col = bn + N0 + nf * 8 + (cq << 1);
        #pragma unroll
        for (int mf = 0; mf < 2; mf++) {
            const int row = bm + M0 + mf * 16 + rq;
            __half* o0 = Cg + (size_t)row * NN + col;
            *(__half2*)o0 = __floats2half2_rn(acc[mf][nf][0] * SPARSITY,
                                              acc[mf][nf][1] * SPARSITY);
            *(__half2*)(o0 + 8 * (size_t)NN) =
                __floats2half2_rn(acc[mf][nf][2] * SPARSITY,
                                  acc[mf][nf][3] * SPARSITY);
        }
    }
}

// ============================================================================
// GEMM2: out[b] = relu(adj[b] @ ST[b]^T + bias).  M=2048, N=256, K=2048.
// CTA 128x256x32, 1 CTA/SM, grid=128 (single wave). 8 warps 2Mx4N, warp 64x64.
// B: 4-stage cp.async. A: fp32 LDG -> cvt -> STS, double-buffered.
// ============================================================================
#define A2_TILE 8192                          // 128 x 32 fp16
#define G2_SM   (4 * B_STAGE + 2 * A2_TILE)   // 81920

__global__ void __launch_bounds__(256, 1) gemm2_kernel(
    const float* __restrict__ adj,
    const __half* __restrict__ ST,
    const float* __restrict__ bias,
    float* __restrict__ out)
{
    extern __shared__ char smem[];
    const uint32_t sb = smem_u32(smem);
    const int t = threadIdx.x, wid = t >> 5, lane = t & 31;
    const int bm = blockIdx.x * 128;
    const int b  = blockIdx.y;

    const float* Ag = adj + (size_t)b * NN * NN;
    const __half* Bg = ST + (size_t)b * DOUT * NN;

    const int M0 = (wid & 1) * 64;
    const int N0 = (wid >> 1) * 64;

    const uint32_t sB0 = sb;
    const uint32_t sA0 = sb + 4 * B_STAGE;

    float acc[4][8][4] = {};
    float4 areg[2][2];     // 2 row-chunks x 2 float4

    auto loadB = [&](int it, int slot) {
        const int k0 = it * TK;
        const uint32_t s0 = sB0 + slot * B_STAGE;
        #pragma unroll
        for (int i = 0; i < 4; i++) {
            int idx = t + 256 * i;
            int r = idx >> 2, c = idx & 3;
            cpasync16(s0 + swz16(r, c), Bg + (size_t)r * NN + k0 + (c << 3));
        }
        asm volatile("cp.async.commit_group;");
    };
    auto ldgA = [&](int it) {
        const int k0 = it * TK;
        #pragma unroll
        for (int s = 0; s < 2; s++) {
            int m = t + 256 * s;                 // chunk id 0..511
            int r = m >> 2, c = m & 3;
            const float* p = Ag + (size_t)(bm + r) * NN + k0 + (c << 3);
            areg[s][0] = *(const float4*)p;
            areg[s][1] = *(const float4*)(p + 4);
        }
    };
    auto stsA = [&](int slot) {
        #pragma unroll
        for (int s = 0; s < 2; s++) {
            int m = t + 256 * s;
            int r = m >> 2, c = m & 3;
            __half2 h[4];
            h[0] = __floats2half2_rn(areg[s][0].x, areg[s][0].y);
            h[1] = __floats2half2_rn(areg[s][0].z, areg[s][0].w);
            h[2] = __floats2half2_rn(areg[s][1].x, areg[s][1].y);
            h[3] = __floats2half2_rn(areg[s][1].z, areg[s][1].w);
            *(uint4*)(smem + 4 * B_STAGE + slot * A2_TILE + swz16(r, c)) =
                *(const uint4*)h;
        }
    };

    const int KITERS = NN / TK;   // 64

    // ---- prologue ----
    ldgA(0);
    loadB(0, 0);
    loadB(1, 1);
    loadB(2, 2);
    stsA(0);
    ldgA(1);
    asm volatile("cp.async.wait_group 2;");
    __syncthreads();

    const int g = lane >> 3, l7 = lane & 7;

    for (int it = 0; it < KITERS; it++) {
        if (it + 3 < KITERS) loadB(it + 3, (it + 3) & 3);
        else asm volatile("cp.async.commit_group;");

        stsA((it + 1) & 1);                    // store A(it+1) into other slot
        ldgA(min(it + 2, KITERS - 1));         // prefetch A(it+2)

        const uint32_t abase = sA0 + (it & 1) * A2_TILE;
        const uint32_t bbase = sB0 + (it & 3) * B_STAGE;

        #pragma unroll
        for (int ks = 0; ks < 2; ks++) {
            uint32_t a[4][4];
            #pragma unroll
            for (int mf = 0; mf < 4; mf++) {
                int row = M0 + mf * 16 + ((g & 1) << 3) + l7;
                int ch  = ks * 2 + (g >> 1);
                ldsm4(a[mf][0], a[mf][1], a[mf][2], a[mf][3], abase + swz16(row, ch));
            }
            uint32_t bf[8][2];
            #pragma unroll
            for (int j8 = 0; j8 < 4; j8++) {
                int row = N0 + j8 * 16 + ((g >> 1) << 3) + l7;
                int ch  = ks * 2 + (g & 1);
                uint32_t r0, r1, r2, r3;
                ldsm4(r0, r1, r2, r3, bbase + swz16(row, ch));
                bf[j8 * 2][0] = r0; bf[j8 * 2][1] = r1;
                bf[j8 * 2 + 1][0] = r2; bf[j8 * 2 + 1][1] = r3;
            }
            #pragma unroll
            for (int mf = 0; mf < 4; mf++)
                #pragma unroll
                for (int nf = 0; nf < 8; nf++)
                    mma_f16(acc[mf][nf], a[mf][0], a[mf][1], a[mf][2], a[mf][3],
                            bf[nf][0], bf[nf][1]);
        }

        asm volatile("cp.async.wait_group 2;");
        __syncthreads();
    }

    // ---- epilogue: bias + relu ----
    const int rq = lane >> 2, cq = lane & 3;
    float* Cg = out + (size_t)b * NN * DOUT;
    #pragma unroll
    for (int nf = 0; nf < 8; nf++) {
        const int col = N0 + nf * 8 + (cq << 1);
        const float2 bv = *(const float2*)(bias + col);
        #pragma unroll
        for (int mf = 0; mf < 4; mf++) {
            const int row = bm + M0 + mf * 16 + rq;
            float* o0 = Cg + (size_t)row * DOUT + col;
            float2 v0, v1;
            v0.x = fmaxf(acc[mf][nf][0] + bv.x, 0.0f);
            v0.y = fmaxf(acc[mf][nf][1] + bv.y, 0.0f);
            v1.x = fmaxf(acc[mf][nf][2] + bv.x, 0.0f);
            v1.y = fmaxf(acc[mf][nf][3] + bv.y, 0.0f);
            *(float2*)o0 = v0;
            *(float2*)(o0 + 8 * DOUT) = v1;
        }
    }
}

// ============================================================================
extern "C" void kernel_launch(void* const* d_in, const int* in_sizes, int n_in,
                              void* d_out, int out_size) {
    const float* x      = (const float*)d_in[0];
    const float* adj    = (const float*)d_in[1];
    const float* weight = (const float*)d_in[2];
    const float* bias   = (const float*)d_in[3];
    float* out = (float*)d_out;

    __half *ST, *WT, *X16;
    cudaGetSymbolAddress((void**)&ST, g_ST);
    cudaGetSymbolAddress((void**)&WT, g_WT);
    cudaGetSymbolAddress((void**)&X16, g_X16);

    prep_kernel<<<64 + (BATCH * NN * DIN) / (256 * 8), 256>>>(weight, WT, x, X16);

    {
        cudaFuncSetAttribute(gemm1_kernel,
                             cudaFuncAttributeMaxDynamicSharedMemorySize, G1_SM);
        dim3 grid(DOUT / 64, NN / 256, BATCH);
        gemm1_kernel<<<grid, 256, G1_SM>>>(WT, X16, ST);
    }
    {
        cudaFuncSetAttribute(gemm2_kernel,
                             cudaFuncAttributeMaxDynamicSharedMemorySize, G2_SM);
        dim3 grid(NN / 128, BATCH, 1);
        gemm2_kernel<<<grid, 256, G2_SM>>>(adj, ST, bias, out);
    }
}

// round 10
// speedup vs baseline: 1.0244x; 1.0244x over previous
#include <cuda_runtime.h>
#include <cuda_fp16.h>
#include <cstdint>

#define SPARSITY 0.01f
#define BATCH 8
#define NN    2048
#define DIN   256
#define DOUT  256

__device__ __half g_SUP[BATCH * NN * DOUT];  // support fp16: [b*node][col]
__device__ __half g_WT[DOUT * DIN];          // sign(quant(W))^T fp16 (+1/0/-1)

__device__ __forceinline__ uint32_t smem_u32(const void* p) {
    uint32_t a;
    asm("{ .reg .u64 t; cvta.to.shared.u64 t, %1; cvt.u32.u64 %0, t; }"
        : "=r"(a) : "l"(p));
    return a;
}

// ---------------- prep: quantW transpose only (tiny) ------------------------
__global__ void __launch_bounds__(256) prep_kernel(
    const float* __restrict__ W, __half* __restrict__ WT)
{
    __shared__ float tile[32][33];
    const int t = threadIdx.x;
    const int tx = t & 31, ty = t >> 5;
    const int o0 = (blockIdx.x & 7) * 32;
    const int i0 = (blockIdx.x >> 3) * 32;
    #pragma unroll
    for (int j = ty; j < 32; j += 8) {
        float w = W[(size_t)(i0 + j) * DOUT + o0 + tx];
        tile[j][tx] = (w > SPARSITY ? 1.0f : 0.0f) + (w < -SPARSITY ? -1.0f : 0.0f);
    }
    __syncthreads();
    #pragma unroll
    for (int j = ty; j < 32; j += 8)
        WT[(size_t)(o0 + j) * DIN + i0 + tx] = __float2half_rn(tile[tx][j]);
}

// ---------------- mma helpers -----------------------------------------------
#define TK 32
__device__ __forceinline__ uint32_t swz16(int row, int c) {
    return (uint32_t)(row * 64 + ((c ^ ((row >> 1) & 3)) << 4));
}
__device__ __forceinline__ void ldsm4(uint32_t& r0, uint32_t& r1, uint32_t& r2,
                                      uint32_t& r3, uint32_t addr) {
    asm volatile("ldmatrix.sync.aligned.m8n8.x4.shared.b16 {%0,%1,%2,%3}, [%4];"
                 : "=r"(r0), "=r"(r1), "=r"(r2), "=r"(r3) : "r"(addr));
}
__device__ __forceinline__ void ldsm4t(uint32_t& r0, uint32_t& r1, uint32_t& r2,
                                       uint32_t& r3, uint32_t addr) {
    asm volatile("ldmatrix.sync.aligned.m8n8.x4.trans.shared.b16 {%0,%1,%2,%3}, [%4];"
                 : "=r"(r0), "=r"(r1), "=r"(r2), "=r"(r3) : "r"(addr));
}
__device__ __forceinline__ void mma_f16(float* d, uint32_t a0, uint32_t a1,
                                        uint32_t a2, uint32_t a3,
                                        uint32_t b0, uint32_t b1) {
    asm volatile(
        "mma.sync.aligned.m16n8k16.row.col.f32.f16.f16.f32 "
        "{%0,%1,%2,%3}, {%4,%5,%6,%7}, {%8,%9}, {%0,%1,%2,%3};"
        : "+f"(d[0]), "+f"(d[1]), "+f"(d[2]), "+f"(d[3])
        : "r"(a0), "r"(a1), "r"(a2), "r"(a3), "r"(b0), "r"(b1));
}
__device__ __forceinline__ void cpasync16(uint32_t dst, const void* src) {
    asm volatile("cp.async.cg.shared.global [%0], [%1], 16;" :: "r"(dst), "l"(src));
}

// ============================================================================
// Unified fp16 GEMM: C[M,N] = A(fp32->fp16)[M,K] @ B(fp16)
//   TRANSB=0: B stored [n][k] K-major.   TRANSB=1: B stored [k][n] row-major.
//   RELU=1:  C fp32 = relu(acc + bias).  RELU=0: C fp16 = acc * SPARSITY.
// CTA 128(M) x 256(N) x 32(K); 256 thr, 8 warps 2Mx4N (warp 64x64).
// B: 4-stage cp.async ring. A: fp32 LDG -> cvt -> STS, double-buffered.
// ============================================================================
#define B_STAGE 16384                         // 32k x 256n (or 256n x 32k) fp16
#define A_TILE  8192                          // 128 x 32 fp16
#define G_SM    (4 * B_STAGE + 2 * A_TILE)    // 81920

template<int KITERS, bool TRANSB, bool RELU>
__global__ void __launch_bounds__(256, 1) mm_kernel(
    const float* __restrict__ Abase, size_t strideA, int lda,
    const __half* __restrict__ Bbase, size_t strideB, int ldb,
    void* __restrict__ Cbase, size_t strideC, int ldc,
    const float* __restrict__ bias)
{
    extern __shared__ char smem[];
    const uint32_t sb = smem_u32(smem);
    const int t = threadIdx.x, wid = t >> 5, lane = t & 31;
    const int bm = blockIdx.x * 128;
    const int b  = blockIdx.y;

    const float*  Ag = Abase + (size_t)b * strideA;
    const __half* Bg = Bbase + (size_t)b * strideB;

    const int M0 = (wid & 1) * 64;
    const int N0 = (wid >> 1) * 64;

    const uint32_t sB0 = sb;
    const uint32_t sA0 = sb + 4 * B_STAGE;

    float acc[4][8][4] = {};
    float4 areg[2][2];

    auto loadB = [&](int it, int slot) {
        const int k0 = it * TK;
        const uint32_t s0 = sB0 + slot * B_STAGE;
        #pragma unroll
        for (int i = 0; i < 4; i++) {
            int c = t + 256 * i;                    // 0..1023 chunks
            if (TRANSB) {
                int k = c >> 5, nch = c & 31;       // row k (node), 16B col chunk
                cpasync16(s0 + k * 512 + ((nch ^ (k & 7)) << 4),
                          Bg + (size_t)(k0 + k) * ldb + (nch << 3));
            } else {
                int r = c >> 2, ch = c & 3;         // row n, 16B k chunk
                cpasync16(s0 + swz16(r, ch),
                          Bg + (size_t)r * ldb + k0 + (ch << 3));
            }
        }
        asm volatile("cp.async.commit_group;");
    };
    auto ldgA = [&](int it) {
        const int k0 = it * TK;
        #pragma unroll
        for (int s = 0; s < 2; s++) {
            int m = t + 256 * s;
            int r = m >> 2, c = m & 3;
            const float* p = Ag + (size_t)(bm + r) * lda + k0 + (c << 3);
            areg[s][0] = *(const float4*)p;
            areg[s][1] = *(const float4*)(p + 4);
        }
    };
    auto stsA = [&](int slot) {
        #pragma unroll
        for (int s = 0; s < 2; s++) {
            int m = t + 256 * s;
            int r = m >> 2, c = m & 3;
            __half2 h[4];
            h[0] = __floats2half2_rn(areg[s][0].x, areg[s][0].y);
            h[1] = __floats2half2_rn(areg[s][0].z, areg[s][0].w);
            h[2] = __floats2half2_rn(areg[s][1].x, areg[s][1].y);
            h[3] = __floats2half2_rn(areg[s][1].z, areg[s][1].w);
            *(uint4*)(smem + 4 * B_STAGE + slot * A_TILE + swz16(r, c)) =
                *(const uint4*)h;
        }
    };

    // ---- prologue ----
    ldgA(0);
    loadB(0, 0);
    loadB(1, 1);
    loadB(2, 2);
    stsA(0);
    ldgA(1);
    asm volatile("cp.async.wait_group 2;");
    __syncthreads();

    const int g = lane >> 3, l7 = lane & 7;

    for (int it = 0; it < KITERS; it++) {
        if (it + 3 < KITERS) loadB(it + 3, (it + 3) & 3);
        else asm volatile("cp.async.commit_group;");

        stsA((it + 1) & 1);
        ldgA(min(it + 2, KITERS - 1));

        const uint32_t abase = sA0 + (it & 1) * A_TILE;
        const uint32_t bbase = sB0 + (it & 3) * B_STAGE;

        #pragma unroll
        for (int ks = 0; ks < 2; ks++) {
            uint32_t a[4][4];
            #pragma unroll
            for (int mf = 0; mf < 4; mf++) {
                int row = M0 + mf * 16 + ((g & 1) << 3) + l7;
                int ch  = ks * 2 + (g >> 1);
                ldsm4(a[mf][0], a[mf][1], a[mf][2], a[mf][3], abase + swz16(row, ch));
            }
            uint32_t bf[8][2];
            #pragma unroll
            for (int j8 = 0; j8 < 4; j8++) {
                uint32_t r0, r1, r2, r3;
                if (TRANSB) {
                    int kl  = ks * 16 + ((g & 1) << 3) + l7;        // k row 0..31
                    int nch = ((N0 + j8 * 16) >> 3) + (g >> 1);     // 16B n-chunk
                    ldsm4t(r0, r1, r2, r3,
                           bbase + kl * 512 + ((nch ^ (kl & 7)) << 4));
                } else {
                    int row = N0 + j8 * 16 + ((g >> 1) << 3) + l7;
                    int ch  = ks * 2 + (g & 1);
                    ldsm4(r0, r1, r2, r3, bbase + swz16(row, ch));
                }
                bf[j8 * 2][0] = r0; bf[j8 * 2][1] = r1;
                bf[j8 * 2 + 1][0] = r2; bf[j8 * 2 + 1][1] = r3;
            }
            #pragma unroll
            for (int mf = 0; mf < 4; mf++)
                #pragma unroll
                for (int nf = 0; nf < 8; nf++)
                    mma_f16(acc[mf][nf], a[mf][0], a[mf][1], a[mf][2], a[mf][3],
                            bf[nf][0], bf[nf][1]);
        }

        asm volatile("cp.async.wait_group 2;");
        __syncthreads();
    }

    // ---- epilogue ----
    const int rq = lane >> 2, cq = lane & 3;
    #pragma unroll
    for (int nf = 0; nf < 8; nf++) {
        const int col = N0 + nf * 8 + (cq << 1);
        float2 bv = make_float2(0.f, 0.f);
        if (RELU) bv = *(const float2*)(bias + col);
        #pragma unroll
        for (int mf = 0; mf < 4; mf++) {
            const int row = bm + M0 + mf * 16 + rq;
            if (RELU) {
                float* Cg = (float*)Cbase + (size_t)b * strideC;
                float* o0 = Cg + (size_t)row * ldc + col;
                float2 v0, v1;
                v0.x = fmaxf(acc[mf][nf][0] + bv.x, 0.0f);
                v0.y = fmaxf(acc[mf][nf][1] + bv.y, 0.0f);
                v1.x = fmaxf(acc[mf][nf][2] + bv.x, 0.0f);
                v1.y = fmaxf(acc[mf][nf][3] + bv.y, 0.0f);
                *(float2*)o0 = v0;
                *(float2*)(o0 + 8 * (size_t)ldc) = v1;
            } else {
                __half* Cg = (__half*)Cbase + (size_t)b * strideC;
                __half* o0 = Cg + (size_t)row * ldc + col;
                *(__half2*)o0 =
                    __floats2half2_rn(acc[mf][nf][0] * SPARSITY,
                                      acc[mf][nf][1] * SPARSITY);
                *(__half2*)(o0 + 8 * (size_t)ldc) =
                    __floats2half2_rn(acc[mf][nf][2] * SPARSITY,
                                      acc[mf][nf][3] * SPARSITY);
            }
        }
    }
}

// ============================================================================
extern "C" void kernel_launch(void* const* d_in, const int* in_sizes, int n_in,
                              void* d_out, int out_size) {
    const float* x      = (const float*)d_in[0];  // [8*2048, 256]
    const float* adj    = (const float*)d_in[1];  // [8, 2048, 2048]
    const float* weight = (const float*)d_in[2];  // [256, 256]
    const float* bias   = (const float*)d_in[3];  // [256]
    float* out = (float*)d_out;                   // [8, 2048, 256]

    __half *SUP, *WT;
    cudaGetSymbolAddress((void**)&SUP, g_SUP);
    cudaGetSymbolAddress((void**)&WT, g_WT);

    // 0) WT = sign(quantize(W))^T
    prep_kernel<<<64, 256>>>(weight, WT);

    // 1) SUP = (x @ Wq) as fp16 [b*node][col]; M=16384, N=256, K=256
    {
        auto k = mm_kernel<DIN / TK, false, false>;
        cudaFuncSetAttribute(k, cudaFuncAttributeMaxDynamicSharedMemorySize, G_SM);
        dim3 grid((BATCH * NN) / 128, 1, 1);
        k<<<grid, 256, G_SM>>>(
            x, 0, DIN,
            WT, 0, DIN,
            SUP, 0, DOUT,
            nullptr);
    }
    // 2) out[b] = relu(adj[b] @ SUP[b] + bias); M=2048, N=256, K=2048
    {
        auto k = mm_kernel<NN / TK, true, true>;
        cudaFuncSetAttribute(k, cudaFuncAttributeMaxDynamicSharedMemorySize, G_SM);
        dim3 grid(NN / 128, BATCH, 1);
        k<<<grid, 256, G_SM>>>(
            adj, (size_t)NN * NN, NN,
            SUP, (size_t)NN * DOUT, DOUT,
            out, (size_t)NN * DOUT, DOUT,
            bias);
    }
}